// round 1
// baseline (speedup 1.0000x reference)
#include <cuda_runtime.h>
#include <cstdint>

#define FT_IN    45056
#define FT_OUT   1024
#define NB       8192
#define FEATS    32
#define STACKS   8
#define FC0_OUT  16

// ---- device scratch (allocation-free: static __device__ globals) ----
__device__ int16_t g_ftw[FT_IN * FT_OUT];            // 92 MB, fits in L2 after quantize
__device__ int8_t  g_fc0[STACKS * FC0_OUT * FT_OUT]; // 128 KB
__device__ int8_t  g_fc1[STACKS * 32 * 32];          // 8 KB
__device__ int8_t  g_fc2[STACKS * 32];               // 256 B

// ---------------------------------------------------------------------------
// Kernel 1: quantize ft_weight (fake_quant bits=16) -> int16 table
// 46137344 elems, 8 per thread, 22528 CTAs x 256 thr
// ---------------------------------------------------------------------------
__global__ __launch_bounds__(256) void quant_ft_kernel(const float* __restrict__ w) {
    int i = (blockIdx.x * 256 + threadIdx.x) * 8;
    float4 a = *reinterpret_cast<const float4*>(w + i);
    float4 b = *reinterpret_cast<const float4*>(w + i + 4);
    float v[8] = {a.x, a.y, a.z, a.w, b.x, b.y, b.z, b.w};
    unsigned int p[4];
#pragma unroll
    for (int k = 0; k < 4; k++) {
        float r0 = fminf(fmaxf(rintf(v[2 * k]),     -32768.f), 32767.f);
        float r1 = fminf(fmaxf(rintf(v[2 * k + 1]), -32768.f), 32767.f);
        unsigned int lo = (unsigned short)(short)(int)r0;
        unsigned int hi = (unsigned short)(short)(int)r1;
        p[k] = lo | (hi << 16);
    }
    uint4 pk = make_uint4(p[0], p[1], p[2], p[3]);
    *reinterpret_cast<uint4*>(g_ftw + i) = pk;
}

// ---------------------------------------------------------------------------
// Kernel 2: quantize fc0/fc1/fc2 weights (fake_quant bits=8) -> int8
// ---------------------------------------------------------------------------
__global__ __launch_bounds__(256) void quant_small_kernel(const float* __restrict__ fc0w,
                                                          const float* __restrict__ fc1w,
                                                          const float* __restrict__ fc2w) {
    const int n0 = STACKS * FC0_OUT * FT_OUT; // 131072
    const int n1 = STACKS * 32 * 32;          // 8192
    const int n2 = STACKS * 32;               // 256
    int i = blockIdx.x * 256 + threadIdx.x;
    if (i < n0) {
        float r = fminf(fmaxf(rintf(fc0w[i]), -128.f), 127.f);
        g_fc0[i] = (int8_t)(int)r;
    } else if (i < n0 + n1) {
        int j = i - n0;
        float r = fminf(fmaxf(rintf(fc1w[j]), -128.f), 127.f);
        g_fc1[j] = (int8_t)(int)r;
    } else if (i < n0 + n1 + n2) {
        int j = i - n0 - n1;
        float r = fminf(fmaxf(rintf(fc2w[j]), -128.f), 127.f);
        g_fc2[j] = (int8_t)(int)r;
    }
}

// ---------------------------------------------------------------------------
// Kernel 3: full NNUE forward, one CTA per batch element, 256 threads
// ---------------------------------------------------------------------------
__global__ __launch_bounds__(256) void nnue_main_kernel(
    const int* __restrict__ wfeats, const int* __restrict__ woff,
    const int* __restrict__ bfeats, const int* __restrict__ boff,
    const int* __restrict__ stm,    const int* __restrict__ bucket,
    const float* __restrict__ ft_bias, const float* __restrict__ psqt,
    const float* __restrict__ fc0_b, const float* __restrict__ fc1_b,
    const float* __restrict__ fc2_b, float* __restrict__ out)
{
    const int b   = blockIdx.x;
    const int tid = threadIdx.x;

    __shared__ float s_stm[FT_OUT];
    __shared__ float s_opp[FT_OUT];
    __shared__ float s_ft[FT_OUT];
    __shared__ float s_red[FC0_OUT][17];
    __shared__ float s_o0[FC0_OUT];
    __shared__ float s_slab[32];
    __shared__ int   s_wfeat[FEATS];
    __shared__ int   s_bfeat[FEATS];

    const int wstart = __ldg(woff + b);
    const int bstart = __ldg(boff + b);
    const int stm_b  = __ldg(stm + b);
    const int bkt    = __ldg(bucket + b);

    if (tid < FEATS)           s_wfeat[tid]         = __ldg(wfeats + wstart + tid);
    else if (tid < 2 * FEATS)  s_bfeat[tid - FEATS] = __ldg(bfeats + bstart + tid - FEATS);
    __syncthreads();

    // ---- feature-transformer gather: 4 dims per thread, int accumulate ----
    const int d = tid * 4;
    int aw0 = 0, aw1 = 0, aw2 = 0, aw3 = 0;
    int ab0 = 0, ab1 = 0, ab2 = 0, ab3 = 0;
#pragma unroll 4
    for (int f = 0; f < FEATS; f++) {
        const uint2 vw = *reinterpret_cast<const uint2*>(g_ftw + s_wfeat[f] * FT_OUT + d);
        aw0 += (short)(vw.x & 0xFFFFu); aw1 += (short)(vw.x >> 16);
        aw2 += (short)(vw.y & 0xFFFFu); aw3 += (short)(vw.y >> 16);
        const uint2 vb = *reinterpret_cast<const uint2*>(g_ftw + s_bfeat[f] * FT_OUT + d);
        ab0 += (short)(vb.x & 0xFFFFu); ab1 += (short)(vb.x >> 16);
        ab2 += (short)(vb.y & 0xFFFFu); ab3 += (short)(vb.y >> 16);
    }
    // bias: fake_quant(30.0, 16) = 30
    float bw[4];
#pragma unroll
    for (int k = 0; k < 4; k++) bw[k] = rintf(__ldg(ft_bias + d + k));
    float accw[4] = {aw0 + bw[0], aw1 + bw[1], aw2 + bw[2], aw3 + bw[3]};
    float accb[4] = {ab0 + bw[0], ab1 + bw[1], ab2 + bw[2], ab3 + bw[3]};

    if (stm_b == 0) {
#pragma unroll
        for (int k = 0; k < 4; k++) { s_stm[d + k] = accw[k]; s_opp[d + k] = accb[k]; }
    } else {
#pragma unroll
        for (int k = 0; k < 4; k++) { s_stm[d + k] = accb[k]; s_opp[d + k] = accw[k]; }
    }
    __syncthreads();

    // ---- pairwise clipped product: ft[0:512] from stm, ft[512:1024] from opp ----
    {
        const int h = tid * 2;
#pragma unroll
        for (int k = 0; k < 2; k++) {
            float x = fminf(fmaxf(s_stm[h + k], 0.f), 127.f);
            float y = fminf(fmaxf(s_stm[h + k + 512], 0.f), 127.f);
            s_ft[h + k] = x * y * (1.f / 128.f);
            float x2 = fminf(fmaxf(s_opp[h + k], 0.f), 127.f);
            float y2 = fminf(fmaxf(s_opp[h + k + 512], 0.f), 127.f);
            s_ft[512 + h + k] = x2 * y2 * (1.f / 128.f);
        }
    }
    __syncthreads();

    // ---- fc0: 16 outputs, 16 partial threads each over 64 elems ----
    {
        const int o = tid >> 4;
        const int part = tid & 15;
        const int8_t* w0 = g_fc0 + (bkt * FC0_OUT + o) * FT_OUT + part * 64;
        const float* fptr = s_ft + part * 64;
        float sum = 0.f;
#pragma unroll
        for (int j = 0; j < 16; j++) {
            char4 c = *reinterpret_cast<const char4*>(w0 + j * 4);
            sum += fptr[j * 4 + 0] * (float)c.x + fptr[j * 4 + 1] * (float)c.y
                 + fptr[j * 4 + 2] * (float)c.z + fptr[j * 4 + 3] * (float)c.w;
        }
        s_red[o][part] = sum;
    }
    __syncthreads();
    if (tid < FC0_OUT) {
        float s = rintf(__ldg(fc0_b + bkt * FC0_OUT + tid)); // fake_quant bits=32
#pragma unroll
        for (int p = 0; p < 16; p++) s += s_red[tid][p];
        s_o0[tid] = s;
    }
    __syncthreads();

    // ---- fc1 / fc2 / psqt / skip on warp 0 ----
    if (tid < 32) {
        // slab: [sqr(15), rel(15), 0, 0]
        float slab;
        if (tid < 15) {
            float v = s_o0[tid];
            slab = fmaxf(fminf(v * v * (1.f / 524288.f), 127.f), 0.f);
        } else if (tid < 30) {
            float v = s_o0[tid - 15];
            slab = fminf(fmaxf(v * (1.f / 64.f), 0.f), 127.f);
        } else {
            slab = 0.f;
        }
        s_slab[tid] = slab;
        __syncwarp();

        // fc1: lane = output
        const int8_t* w1 = g_fc1 + (bkt * 32 + tid) * 32;
        float o1 = rintf(__ldg(fc1_b + bkt * 32 + tid));
#pragma unroll
        for (int i = 0; i < 32; i++) o1 += s_slab[i] * (float)w1[i];
        float ac1 = fminf(fmaxf(o1 * (1.f / 64.f), 0.f), 127.f);

        // fc2: lane = input, warp reduce
        float p2 = ac1 * (float)g_fc2[bkt * 32 + tid];
#pragma unroll
        for (int off = 16; off; off >>= 1) p2 += __shfl_xor_sync(0xFFFFFFFFu, p2, off);

        // psqt: lane = feature (FEATS == 32), column = bucket
        float pw = rintf(__ldg(psqt + s_wfeat[tid] * 8 + bkt));
        float pb = rintf(__ldg(psqt + s_bfeat[tid] * 8 + bkt));
        float dwb = pw - pb; // sum_w - sum_b after reduce
#pragma unroll
        for (int off = 16; off; off >>= 1) dwb += __shfl_xor_sync(0xFFFFFFFFu, dwb, off);

        if (tid == 0) {
            float scalar = p2 + rintf(__ldg(fc2_b + bkt));
            float skip   = s_o0[15] * (9600.f / 8128.f);
            float psqt_v = (stm_b == 0 ? dwb : -dwb) * 0.5f;
            out[b] = (psqt_v + scalar + skip) * (1.f / 16.f);
        }
    }
}

// ---------------------------------------------------------------------------
// launch
// ---------------------------------------------------------------------------
extern "C" void kernel_launch(void* const* d_in, const int* in_sizes, int n_in,
                              void* d_out, int out_size) {
    const int*   w_feats  = (const int*)  d_in[0];
    const int*   w_off    = (const int*)  d_in[1];
    const int*   b_feats  = (const int*)  d_in[2];
    const int*   b_off    = (const int*)  d_in[3];
    const int*   stm      = (const int*)  d_in[4];
    const int*   bucket   = (const int*)  d_in[5];
    const float* ftw      = (const float*)d_in[6];
    const float* ftb      = (const float*)d_in[7];
    const float* psqt     = (const float*)d_in[8];
    const float* fc0w     = (const float*)d_in[9];
    const float* fc0b     = (const float*)d_in[10];
    const float* fc1w     = (const float*)d_in[11];
    const float* fc1b     = (const float*)d_in[12];
    const float* fc2w     = (const float*)d_in[13];
    const float* fc2b     = (const float*)d_in[14];
    float* out = (float*)d_out;

    // quantize ft table: 46137344 elems / (256 thr * 8 elems) = 22528 CTAs
    quant_ft_kernel<<<22528, 256>>>(ftw);
    // quantize small fc weights: 131072 + 8192 + 256 = 139520 elems
    quant_small_kernel<<<(139520 + 255) / 256, 256>>>(fc0w, fc1w, fc2w);
    // main forward
    nnue_main_kernel<<<NB, 256>>>(w_feats, w_off, b_feats, b_off, stm, bucket,
                                  ftb, psqt, fc0b, fc1b, fc2b, out);
}

// round 10
// speedup vs baseline: 1.1249x; 1.1249x over previous
#include <cuda_runtime.h>
#include <cstdint>

#define FT_IN    45056
#define FT_OUT   1024
#define NB       8192
#define FEATS    32
#define STACKS   8
#define FC0_OUT  16

// ---- device scratch (allocation-free: static __device__ globals) ----
__device__ int8_t g_ftw8[FT_IN * FT_OUT];             // 46 MB int8 table, L2-resident
__device__ int8_t g_fc0[STACKS * FC0_OUT * FT_OUT];   // 128 KB
__device__ int8_t g_fc1[STACKS * 32 * 32];            // 8 KB
__device__ int8_t g_fc2[STACKS * 32];                 // 256 B

// ---------------------------------------------------------------------------
// Kernel 1: quantize ft_weight -> int8 (exact vs 16-bit fake_quant: |w|<~30)
// 46137344 elems, 16 per thread -> 11264 CTAs x 256 thr
// ---------------------------------------------------------------------------
__global__ __launch_bounds__(256) void quant_ft_kernel(const float* __restrict__ w) {
    const int i = (blockIdx.x * 256 + threadIdx.x) * 16;
    unsigned int packed[4];
#pragma unroll
    for (int q = 0; q < 4; q++) {
        float4 a = *reinterpret_cast<const float4*>(w + i + q * 4);
        int b0 = (int)fminf(fmaxf(rintf(a.x), -128.f), 127.f);
        int b1 = (int)fminf(fmaxf(rintf(a.y), -128.f), 127.f);
        int b2 = (int)fminf(fmaxf(rintf(a.z), -128.f), 127.f);
        int b3 = (int)fminf(fmaxf(rintf(a.w), -128.f), 127.f);
        packed[q] = (b0 & 0xFF) | ((b1 & 0xFF) << 8) | ((b2 & 0xFF) << 16) | ((b3 & 0xFF) << 24);
    }
    *reinterpret_cast<uint4*>(g_ftw8 + i) = make_uint4(packed[0], packed[1], packed[2], packed[3]);
}

// ---------------------------------------------------------------------------
// Kernel 2: quantize fc0/fc1/fc2 weights (fake_quant bits=8) -> int8
// ---------------------------------------------------------------------------
__global__ __launch_bounds__(256) void quant_small_kernel(const float* __restrict__ fc0w,
                                                          const float* __restrict__ fc1w,
                                                          const float* __restrict__ fc2w) {
    const int n0 = STACKS * FC0_OUT * FT_OUT; // 131072
    const int n1 = STACKS * 32 * 32;          // 8192
    const int n2 = STACKS * 32;               // 256
    int i = blockIdx.x * 256 + threadIdx.x;
    if (i < n0) {
        g_fc0[i] = (int8_t)(int)fminf(fmaxf(rintf(fc0w[i]), -128.f), 127.f);
    } else if (i < n0 + n1) {
        int j = i - n0;
        g_fc1[j] = (int8_t)(int)fminf(fmaxf(rintf(fc1w[j]), -128.f), 127.f);
    } else if (i < n0 + n1 + n2) {
        int j = i - n0 - n1;
        g_fc2[j] = (int8_t)(int)fminf(fmaxf(rintf(fc2w[j]), -128.f), 127.f);
    }
}

// ---------------------------------------------------------------------------
// Kernel 3: full NNUE forward, one CTA per batch element, 256 threads.
// Threads 0-127: w-perspective (8 dims each); 128-255: b-perspective.
// ---------------------------------------------------------------------------
__global__ __launch_bounds__(256) void nnue_main_kernel(
    const int* __restrict__ wfeats, const int* __restrict__ woff,
    const int* __restrict__ bfeats, const int* __restrict__ boff,
    const int* __restrict__ stm,    const int* __restrict__ bucket,
    const float* __restrict__ ft_bias, const float* __restrict__ psqt,
    const float* __restrict__ fc0_b, const float* __restrict__ fc1_b,
    const float* __restrict__ fc2_b, float* __restrict__ out)
{
    const int b   = blockIdx.x;
    const int tid = threadIdx.x;

    __shared__ float s_stm[FT_OUT];
    __shared__ float s_opp[FT_OUT];
    __shared__ float s_ft[FT_OUT];
    __shared__ float s_red[FC0_OUT][17];
    __shared__ float s_o0[FC0_OUT];
    __shared__ float s_slab[32];
    __shared__ int   s_feat[2 * FEATS];   // [0:32)=w, [32:64)=b

    const int wstart = __ldg(woff + b);
    const int bstart = __ldg(boff + b);
    const int stm_b  = __ldg(stm + b);
    const int bkt    = __ldg(bucket + b);

    if (tid < FEATS)           s_feat[tid] = __ldg(wfeats + wstart + tid);
    else if (tid < 2 * FEATS)  s_feat[tid] = __ldg(bfeats + bstart + tid - FEATS);
    __syncthreads();

    // ---- feature-transformer gather: int8 rows, dp4a accumulate ----
    const int p = tid >> 7;              // 0 = w, 1 = b
    const int d = (tid & 127) * 8;
    const int* feat = s_feat + p * FEATS;
    int a0 = 0, a1 = 0, a2 = 0, a3 = 0, a4 = 0, a5 = 0, a6 = 0, a7 = 0;
#pragma unroll 8
    for (int f = 0; f < FEATS; f++) {
        const uint2 v = *reinterpret_cast<const uint2*>(g_ftw8 + feat[f] * FT_OUT + d);
        a0 = __dp4a((int)v.x, 0x00000001, a0);
        a1 = __dp4a((int)v.x, 0x00000100, a1);
        a2 = __dp4a((int)v.x, 0x00010000, a2);
        a3 = __dp4a((int)v.x, 0x01000000, a3);
        a4 = __dp4a((int)v.y, 0x00000001, a4);
        a5 = __dp4a((int)v.y, 0x00000100, a5);
        a6 = __dp4a((int)v.y, 0x00010000, a6);
        a7 = __dp4a((int)v.y, 0x01000000, a7);
    }
    // + bias (fake_quant(ft_bias,16) = rint), route to stm/opp by perspective
    float* dst = ((p == 0) == (stm_b == 0)) ? s_stm : s_opp;
    int acc[8] = {a0, a1, a2, a3, a4, a5, a6, a7};
#pragma unroll
    for (int k = 0; k < 8; k++)
        dst[d + k] = (float)acc[k] + rintf(__ldg(ft_bias + d + k));
    __syncthreads();

    // ---- pairwise clipped product: ft[0:512] from stm, ft[512:1024] from opp ----
    {
        const int h = tid * 2;
#pragma unroll
        for (int k = 0; k < 2; k++) {
            float x = fminf(fmaxf(s_stm[h + k], 0.f), 127.f);
            float y = fminf(fmaxf(s_stm[h + k + 512], 0.f), 127.f);
            s_ft[h + k] = x * y * (1.f / 128.f);
            float x2 = fminf(fmaxf(s_opp[h + k], 0.f), 127.f);
            float y2 = fminf(fmaxf(s_opp[h + k + 512], 0.f), 127.f);
            s_ft[512 + h + k] = x2 * y2 * (1.f / 128.f);
        }
    }
    __syncthreads();

    // ---- fc0: 16 outputs, 16 partial threads each over 64 elems ----
    {
        const int o = tid >> 4;
        const int part = tid & 15;
        const int8_t* w0 = g_fc0 + (bkt * FC0_OUT + o) * FT_OUT + part * 64;
        const float* fptr = s_ft + part * 64;
        float sum = 0.f;
#pragma unroll
        for (int j = 0; j < 16; j++) {
            char4 c = *reinterpret_cast<const char4*>(w0 + j * 4);
            sum += fptr[j * 4 + 0] * (float)c.x + fptr[j * 4 + 1] * (float)c.y
                 + fptr[j * 4 + 2] * (float)c.z + fptr[j * 4 + 3] * (float)c.w;
        }
        s_red[o][part] = sum;
    }
    __syncthreads();
    if (tid < FC0_OUT) {
        float s = rintf(__ldg(fc0_b + bkt * FC0_OUT + tid)); // fake_quant bits=32
#pragma unroll
        for (int pp = 0; pp < 16; pp++) s += s_red[tid][pp];
        s_o0[tid] = s;
    }
    __syncthreads();

    // ---- fc1 / fc2 / psqt / skip on warp 0 ----
    if (tid < 32) {
        float slab;
        if (tid < 15) {
            float v = s_o0[tid];
            slab = fmaxf(fminf(v * v * (1.f / 524288.f), 127.f), 0.f);
        } else if (tid < 30) {
            float v = s_o0[tid - 15];
            slab = fminf(fmaxf(v * (1.f / 64.f), 0.f), 127.f);
        } else {
            slab = 0.f;
        }
        s_slab[tid] = slab;
        __syncwarp();

        const int8_t* w1 = g_fc1 + (bkt * 32 + tid) * 32;
        float o1 = rintf(__ldg(fc1_b + bkt * 32 + tid));
#pragma unroll
        for (int i = 0; i < 32; i++) o1 += s_slab[i] * (float)w1[i];
        float ac1 = fminf(fmaxf(o1 * (1.f / 64.f), 0.f), 127.f);

        float p2 = ac1 * (float)g_fc2[bkt * 32 + tid];
#pragma unroll
        for (int off = 16; off; off >>= 1) p2 += __shfl_xor_sync(0xFFFFFFFFu, p2, off);

        float pw = rintf(__ldg(psqt + s_feat[tid] * 8 + bkt));
        float pb = rintf(__ldg(psqt + s_feat[FEATS + tid] * 8 + bkt));
        float dwb = pw - pb;
#pragma unroll
        for (int off = 16; off; off >>= 1) dwb += __shfl_xor_sync(0xFFFFFFFFu, dwb, off);

        if (tid == 0) {
            float scalar = p2 + rintf(__ldg(fc2_b + bkt));
            float skip   = s_o0[15] * (9600.f / 8128.f);
            float psqt_v = (stm_b == 0 ? dwb : -dwb) * 0.5f;
            out[b] = (psqt_v + scalar + skip) * (1.f / 16.f);
        }
    }
}

// ---------------------------------------------------------------------------
// launch
// ---------------------------------------------------------------------------
extern "C" void kernel_launch(void* const* d_in, const int* in_sizes, int n_in,
                              void* d_out, int out_size) {
    const int*   w_feats  = (const int*)  d_in[0];
    const int*   w_off    = (const int*)  d_in[1];
    const int*   b_feats  = (const int*)  d_in[2];
    const int*   b_off    = (const int*)  d_in[3];
    const int*   stm      = (const int*)  d_in[4];
    const int*   bucket   = (const int*)  d_in[5];
    const float* ftw      = (const float*)d_in[6];
    const float* ftb      = (const float*)d_in[7];
    const float* psqt     = (const float*)d_in[8];
    const float* fc0w     = (const float*)d_in[9];
    const float* fc0b     = (const float*)d_in[10];
    const float* fc1w     = (const float*)d_in[11];
    const float* fc1b     = (const float*)d_in[12];
    const float* fc2w     = (const float*)d_in[13];
    const float* fc2b     = (const float*)d_in[14];
    float* out = (float*)d_out;

    // quantize ft table: 46137344 elems / (256 thr * 16 elems) = 11264 CTAs
    quant_ft_kernel<<<11264, 256>>>(ftw);
    // quantize small fc weights
    quant_small_kernel<<<(139520 + 255) / 256, 256>>>(fc0w, fc1w, fc2w);
    // main forward
    nnue_main_kernel<<<NB, 256>>>(w_feats, w_off, b_feats, b_off, stm, bucket,
                                  ftb, psqt, fc0b, fc1b, fc2b, out);
}

// round 15
// speedup vs baseline: 1.7758x; 1.5786x over previous
#include <cuda_runtime.h>
#include <cstdint>

#define FT_IN    45056
#define FT_OUT   1024
#define NB       8192
#define FEATS    32
#define STACKS   8
#define FC0_OUT  16

// ---- device scratch (allocation-free: static __device__ globals) ----
__device__ int8_t g_ftw8[FT_IN * FT_OUT];             // 46 MB int8 table, L2-resident
__device__ int8_t g_fc0[STACKS * FC0_OUT * FT_OUT];   // 128 KB
__device__ int8_t g_fc1[STACKS * 32 * 32];            // 8 KB
__device__ int8_t g_fc2[STACKS * 32];                 // 256 B

// ---------------------------------------------------------------------------
// Kernel 1: quantize ft_weight -> int8 (exact vs 16-bit fake_quant: |w|<~30)
// ---------------------------------------------------------------------------
__global__ __launch_bounds__(256) void quant_ft_kernel(const float* __restrict__ w) {
    const int i = (blockIdx.x * 256 + threadIdx.x) * 16;
    unsigned int packed[4];
#pragma unroll
    for (int q = 0; q < 4; q++) {
        float4 a = *reinterpret_cast<const float4*>(w + i + q * 4);
        int b0 = (int)fminf(fmaxf(rintf(a.x), -128.f), 127.f);
        int b1 = (int)fminf(fmaxf(rintf(a.y), -128.f), 127.f);
        int b2 = (int)fminf(fmaxf(rintf(a.z), -128.f), 127.f);
        int b3 = (int)fminf(fmaxf(rintf(a.w), -128.f), 127.f);
        packed[q] = (b0 & 0xFF) | ((b1 & 0xFF) << 8) | ((b2 & 0xFF) << 16) | ((b3 & 0xFF) << 24);
    }
    *reinterpret_cast<uint4*>(g_ftw8 + i) = make_uint4(packed[0], packed[1], packed[2], packed[3]);
}

// ---------------------------------------------------------------------------
// Kernel 2: quantize fc0/fc1/fc2 weights (fake_quant bits=8) -> int8
// ---------------------------------------------------------------------------
__global__ __launch_bounds__(256) void quant_small_kernel(const float* __restrict__ fc0w,
                                                          const float* __restrict__ fc1w,
                                                          const float* __restrict__ fc2w) {
    const int n0 = STACKS * FC0_OUT * FT_OUT; // 131072
    const int n1 = STACKS * 32 * 32;          // 8192
    const int n2 = STACKS * 32;               // 256
    int i = blockIdx.x * 256 + threadIdx.x;
    if (i < n0) {
        g_fc0[i] = (int8_t)(int)fminf(fmaxf(rintf(fc0w[i]), -128.f), 127.f);
    } else if (i < n0 + n1) {
        int j = i - n0;
        g_fc1[j] = (int8_t)(int)fminf(fmaxf(rintf(fc1w[j]), -128.f), 127.f);
    } else if (i < n0 + n1 + n2) {
        int j = i - n0 - n1;
        g_fc2[j] = (int8_t)(int)fminf(fmaxf(rintf(fc2w[j]), -128.f), 127.f);
    }
}

// ---------------------------------------------------------------------------
// Kernel 3: full NNUE forward, one CTA per batch element, 256 threads.
// ---------------------------------------------------------------------------
__global__ __launch_bounds__(256) void nnue_main_kernel(
    const int* __restrict__ wfeats, const int* __restrict__ woff,
    const int* __restrict__ bfeats, const int* __restrict__ boff,
    const int* __restrict__ stm,    const int* __restrict__ bucket,
    const float* __restrict__ ft_bias, const float* __restrict__ psqt,
    const float* __restrict__ fc0_b, const float* __restrict__ fc1_b,
    const float* __restrict__ fc2_b, float* __restrict__ out)
{
    const int b   = blockIdx.x;
    const int tid = threadIdx.x;

    __shared__ float s_stm[FT_OUT];
    __shared__ float s_opp[FT_OUT];
    __shared__ __align__(16) float s_ft[FT_OUT];
    __shared__ float s_red[FC0_OUT][17];
    __shared__ float s_o0[FC0_OUT];
    __shared__ float s_slab[32];
    __shared__ int   s_feat[2 * FEATS];   // [0:32)=w, [32:64)=b

    const int wstart = __ldg(woff + b);
    const int bstart = __ldg(boff + b);
    const int stm_b  = __ldg(stm + b);
    const int bkt    = __ldg(bucket + b);

    if (tid < FEATS)           s_feat[tid] = __ldg(wfeats + wstart + tid);
    else if (tid < 2 * FEATS)  s_feat[tid] = __ldg(bfeats + bstart + tid - FEATS);
    __syncthreads();

    // ---- feature-transformer gather: int8 rows, dp4a accumulate ----
    const int p = tid >> 7;              // 0 = w, 1 = b
    const int d = (tid & 127) * 8;
    const int* feat = s_feat + p * FEATS;
    int a0 = 0, a1 = 0, a2 = 0, a3 = 0, a4 = 0, a5 = 0, a6 = 0, a7 = 0;
#pragma unroll 8
    for (int f = 0; f < FEATS; f++) {
        const uint2 v = *reinterpret_cast<const uint2*>(g_ftw8 + feat[f] * FT_OUT + d);
        a0 = __dp4a((int)v.x, 0x00000001, a0);
        a1 = __dp4a((int)v.x, 0x00000100, a1);
        a2 = __dp4a((int)v.x, 0x00010000, a2);
        a3 = __dp4a((int)v.x, 0x01000000, a3);
        a4 = __dp4a((int)v.y, 0x00000001, a4);
        a5 = __dp4a((int)v.y, 0x00000100, a5);
        a6 = __dp4a((int)v.y, 0x00010000, a6);
        a7 = __dp4a((int)v.y, 0x01000000, a7);
    }
    // + bias (fake_quant(ft_bias,16) = rint), route to stm/opp by perspective
    float* dst = ((p == 0) == (stm_b == 0)) ? s_stm : s_opp;
    int acc[8] = {a0, a1, a2, a3, a4, a5, a6, a7};
#pragma unroll
    for (int k = 0; k < 8; k++)
        dst[d + k] = (float)acc[k] + rintf(__ldg(ft_bias + d + k));
    __syncthreads();

    // ---- pairwise clipped product: ft[0:512] from stm, ft[512:1024] from opp ----
    {
        const int h = tid * 2;
#pragma unroll
        for (int k = 0; k < 2; k++) {
            float x = fminf(fmaxf(s_stm[h + k], 0.f), 127.f);
            float y = fminf(fmaxf(s_stm[h + k + 512], 0.f), 127.f);
            s_ft[h + k] = x * y * (1.f / 128.f);
            float x2 = fminf(fmaxf(s_opp[h + k], 0.f), 127.f);
            float y2 = fminf(fmaxf(s_opp[h + k + 512], 0.f), 127.f);
            s_ft[512 + h + k] = x2 * y2 * (1.f / 128.f);
        }
    }
    __syncthreads();

    // ---- fc0: 16 outputs x 16 partial threads; conflict-free interleaved walk.
    // Thread (o,part) sums elements {m*64 + part*4 + k}; warp LDS addresses are
    // 16B-stride consecutive (conflict-free) instead of 256B-stride (16-way).
    {
        const int o = tid >> 4;
        const int part = tid & 15;
        const int8_t* w0 = g_fc0 + (bkt * FC0_OUT + o) * FT_OUT;
        float sum0 = 0.f, sum1 = 0.f;
#pragma unroll
        for (int m = 0; m < 16; m++) {
            const int off = m * 64 + part * 4;
            char4  c = *reinterpret_cast<const char4*>(w0 + off);
            float4 v = *reinterpret_cast<const float4*>(s_ft + off);
            sum0 += v.x * (float)c.x + v.y * (float)c.y;
            sum1 += v.z * (float)c.z + v.w * (float)c.w;
        }
        s_red[o][part] = sum0 + sum1;
    }
    __syncthreads();
    if (tid < FC0_OUT) {
        float s = rintf(__ldg(fc0_b + bkt * FC0_OUT + tid)); // fake_quant bits=32
#pragma unroll
        for (int pp = 0; pp < 16; pp++) s += s_red[tid][pp];
        s_o0[tid] = s;
    }
    __syncthreads();

    // ---- fc1 / fc2 / psqt / skip on warp 0 ----
    if (tid < 32) {
        float slab;
        if (tid < 15) {
            float v = s_o0[tid];
            slab = fmaxf(fminf(v * v * (1.f / 524288.f), 127.f), 0.f);
        } else if (tid < 30) {
            float v = s_o0[tid - 15];
            slab = fminf(fmaxf(v * (1.f / 64.f), 0.f), 127.f);
        } else {
            slab = 0.f;
        }
        s_slab[tid] = slab;
        __syncwarp();

        // fc1: lane = output; char4 weight loads + 4-way ILP partial sums
        const int8_t* w1 = g_fc1 + (bkt * 32 + tid) * 32;
        float p0 = 0.f, p1 = 0.f, p2s = 0.f, p3 = 0.f;
#pragma unroll
        for (int i = 0; i < 32; i += 4) {
            char4 c = *reinterpret_cast<const char4*>(w1 + i);
            p0 += s_slab[i + 0] * (float)c.x;
            p1 += s_slab[i + 1] * (float)c.y;
            p2s += s_slab[i + 2] * (float)c.z;
            p3 += s_slab[i + 3] * (float)c.w;
        }
        float o1 = rintf(__ldg(fc1_b + bkt * 32 + tid)) + (p0 + p1) + (p2s + p3);
        float ac1 = fminf(fmaxf(o1 * (1.f / 64.f), 0.f), 127.f);

        float p2 = ac1 * (float)g_fc2[bkt * 32 + tid];
#pragma unroll
        for (int off = 16; off; off >>= 1) p2 += __shfl_xor_sync(0xFFFFFFFFu, p2, off);

        float pw = rintf(__ldg(psqt + s_feat[tid] * 8 + bkt));
        float pb = rintf(__ldg(psqt + s_feat[FEATS + tid] * 8 + bkt));
        float dwb = pw - pb;
#pragma unroll
        for (int off = 16; off; off >>= 1) dwb += __shfl_xor_sync(0xFFFFFFFFu, dwb, off);

        if (tid == 0) {
            float scalar = p2 + rintf(__ldg(fc2_b + bkt));
            float skip   = s_o0[15] * (9600.f / 8128.f);
            float psqt_v = (stm_b == 0 ? dwb : -dwb) * 0.5f;
            out[b] = (psqt_v + scalar + skip) * (1.f / 16.f);
        }
    }
}

// ---------------------------------------------------------------------------
// launch
// ---------------------------------------------------------------------------
extern "C" void kernel_launch(void* const* d_in, const int* in_sizes, int n_in,
                              void* d_out, int out_size) {
    const int*   w_feats  = (const int*)  d_in[0];
    const int*   w_off    = (const int*)  d_in[1];
    const int*   b_feats  = (const int*)  d_in[2];
    const int*   b_off    = (const int*)  d_in[3];
    const int*   stm      = (const int*)  d_in[4];
    const int*   bucket   = (const int*)  d_in[5];
    const float* ftw      = (const float*)d_in[6];
    const float* ftb      = (const float*)d_in[7];
    const float* psqt     = (const float*)d_in[8];
    const float* fc0w     = (const float*)d_in[9];
    const float* fc0b     = (const float*)d_in[10];
    const float* fc1w     = (const float*)d_in[11];
    const float* fc1b     = (const float*)d_in[12];
    const float* fc2w     = (const float*)d_in[13];
    const float* fc2b     = (const float*)d_in[14];
    float* out = (float*)d_out;

    quant_ft_kernel<<<11264, 256>>>(ftw);
    quant_small_kernel<<<(139520 + 255) / 256, 256>>>(fc0w, fc1w, fc2w);
    nnue_main_kernel<<<NB, 256>>>(w_feats, w_off, b_feats, b_off, stm, bucket,
                                  ftb, psqt, fc0b, fc1b, fc2b, out);
}